// round 10
// baseline (speedup 1.0000x reference)
#include <cuda_runtime.h>

// Problem constants (fixed shapes from reference setup_inputs)
#define NS   262144      // B*T*C samples
#define NEL  16777216    // B*T*C*F elements for reconstruction loss
#define KK   8           // mixture components
#define DD   8           // latent dim
#define NTRI 36          // D*(D+1)/2 upper-triangular entries
#define MPK  45          // per-k moment slots: gsum(1) + sz(8) + s2(36)

#define LAMBDA_ENERGY 0.1
#define LAMBDA_COV    0.005

// Register budget per SM is 64K: moments (1/SM @64regs = 16K) + reconst
// (5/SM @32regs = 40K) co-reside; energy (2/SM @64regs = 32K) overlaps
// reconst's remainder. This is the whole point of this round.
#define RECONST_BLOCKS 740
#define MOMENT_BLOCKS  148
#define ENERGY_BLOCKS  296
#define DONE_TARGET    (RECONST_BLOCKS + ENERGY_BLOCKS)

// ---------------- device scratch (zero-initialized at module load; the
// finalizing block re-zeroes everything dirtied, so each graph replay starts
// clean without a zeroing launch) ----------------
__device__ double g_mom[KK * MPK];   // [k][0]=gsum, [1..8]=sum(g*z), [9..44]=sum(g*zi*zj)
__device__ double g_reconst;         // sum of squared diffs
__device__ double g_energy;          // sum of per-sample energies
__device__ double g_base;            // lambda_cov*cov_diag (overwritten each run)
__device__ float  g_w2[KK * NTRI];   // quad coeffs (overwritten each run)
__device__ float  g_bv[KK * DD];     // C*mu (overwritten)
__device__ float  g_cst[KK];         // -0.5*mu^T C mu + log(c_k) (overwritten)
__device__ unsigned g_mctr;          // moments last-block counter
__device__ unsigned g_done;          // completion counter (reconst + energy blocks)

// upper-tri row starts for D=8: t(i,j) = TRI_ROW[i] + (j - i), j >= i
__device__ __constant__ int TRI_ROW[8] = {0, 8, 15, 21, 26, 30, 33, 35};

__device__ __forceinline__ float warp_reduce(float v) {
#pragma unroll
    for (int o = 16; o > 0; o >>= 1) v += __shfl_xor_sync(0xFFFFFFFFu, v, o);
    return v;
}

// finalize-if-last: every terminal block (reconst + energy) calls this after
// its atomicAdd of partials. The globally LAST block writes the scalar and
// resets all replay state. g_base is valid because stats ran (in moments'
// last block) before any energy block could finish.
__device__ __forceinline__ void finish_and_maybe_finalize(float* out) {
    __shared__ unsigned s_last;
    if (threadIdx.x == 0) {
        __threadfence();
        unsigned prev = atomicAdd(&g_done, 1u);
        s_last = (prev == (unsigned)(DONE_TARGET - 1)) ? 1u : 0u;
    }
    __syncthreads();
    if (s_last) {
        if (threadIdx.x == 0) {
            __threadfence();
            double rm = g_reconst / (double)NEL;
            double e  = *((volatile double*)&g_energy);
            out[0] = (float)(rm + g_base + LAMBDA_ENERGY * (e / (double)NS));
            g_reconst = 0.0;
            g_energy = 0.0;
            g_done = 0u;
        }
        for (int i = threadIdx.x; i < KK * MPK; i += blockDim.x) g_mom[i] = 0.0;
    }
}

// ---------------- main stream: reconstruction sum (pure HBM stream) --------
__global__ void __launch_bounds__(256, 5) reconst_kernel(
    const float4* __restrict__ x, const float4* __restrict__ xh,
    float* __restrict__ out) {
    const int n4 = NEL / 4;
    float acc0 = 0.0f, acc1 = 0.0f;
    int i = blockIdx.x * 256 + threadIdx.x;
    const int stride = RECONST_BLOCKS * 256;
    for (; i + stride < n4; i += 2 * stride) {
        float4 a0 = x[i], b0 = xh[i];
        float4 a1 = x[i + stride], b1 = xh[i + stride];
        float d;
        d = b0.x - a0.x; acc0 = fmaf(d, d, acc0);
        d = b0.y - a0.y; acc0 = fmaf(d, d, acc0);
        d = b0.z - a0.z; acc0 = fmaf(d, d, acc0);
        d = b0.w - a0.w; acc0 = fmaf(d, d, acc0);
        d = b1.x - a1.x; acc1 = fmaf(d, d, acc1);
        d = b1.y - a1.y; acc1 = fmaf(d, d, acc1);
        d = b1.z - a1.z; acc1 = fmaf(d, d, acc1);
        d = b1.w - a1.w; acc1 = fmaf(d, d, acc1);
    }
    for (; i < n4; i += stride) {
        float4 a = x[i], b = xh[i];
        float d;
        d = b.x - a.x; acc0 = fmaf(d, d, acc0);
        d = b.y - a.y; acc0 = fmaf(d, d, acc0);
        d = b.z - a.z; acc0 = fmaf(d, d, acc0);
        d = b.w - a.w; acc0 = fmaf(d, d, acc0);
    }
    __shared__ float red[8];
    float v = warp_reduce(acc0 + acc1);
    int lane = threadIdx.x & 31, wid = threadIdx.x >> 5;
    if (lane == 0) red[wid] = v;
    __syncthreads();
    if (threadIdx.x == 0) {
        float s = 0.0f;
#pragma unroll
        for (int w = 0; w < 8; w++) s += red[w];
        atomicAdd(&g_reconst, (double)s);
    }
    finish_and_maybe_finalize(out);
}

// ---------------- side stream: GMM moments, stats fused into last block ----
// 1 block/SM (16K regs) so it co-resides with reconst. 8 lanes per
// sample-slot (one per k); ~56 samples per thread gives per-warp MLP.
__global__ void __launch_bounds__(256, 4) moments_kernel(
    const float* __restrict__ z, const float* __restrict__ gamma) {
    const int lane = threadIdx.x & 31;
    const int k = lane & 7;
    const int warp = threadIdx.x >> 5;                 // 0..7
    const int slot = (blockIdx.x * 256 + threadIdx.x) >> 3;
    const int stride = (MOMENT_BLOCKS * 256) >> 3;

    float gs = 0.0f;
    float sz[DD];
    float s2[NTRI];
#pragma unroll
    for (int i = 0; i < DD; i++) sz[i] = 0.0f;
#pragma unroll
    for (int t = 0; t < NTRI; t++) s2[t] = 0.0f;

    for (int n = slot; n < NS; n += stride) {
        float4 z0 = *reinterpret_cast<const float4*>(z + (size_t)n * 8);
        float4 z1 = *reinterpret_cast<const float4*>(z + (size_t)n * 8 + 4);
        float zz[8] = {z0.x, z0.y, z0.z, z0.w, z1.x, z1.y, z1.z, z1.w};
        float g = __ldg(gamma + (size_t)n * 8 + k);
        gs += g;
        float gz[8];
#pragma unroll
        for (int i = 0; i < 8; i++) { gz[i] = g * zz[i]; sz[i] += gz[i]; }
        int t = 0;
#pragma unroll
        for (int i = 0; i < 8; i++)
#pragma unroll
            for (int j = i; j < 8; j++) { s2[t] = fmaf(gz[i], zz[j], s2[t]); t++; }
    }

    const unsigned m = 0xFFFFFFFFu;
    gs += __shfl_xor_sync(m, gs, 8);  gs += __shfl_xor_sync(m, gs, 16);
#pragma unroll
    for (int i = 0; i < DD; i++) {
        sz[i] += __shfl_xor_sync(m, sz[i], 8);
        sz[i] += __shfl_xor_sync(m, sz[i], 16);
    }
#pragma unroll
    for (int t = 0; t < NTRI; t++) {
        s2[t] += __shfl_xor_sync(m, s2[t], 8);
        s2[t] += __shfl_xor_sync(m, s2[t], 16);
    }

    __shared__ float sacc[8][KK * MPK];   // 11.5 KB
    if (lane < 8) {
        float* p = &sacc[warp][k * MPK];
        p[0] = gs;
#pragma unroll
        for (int i = 0; i < DD; i++) p[1 + i] = sz[i];
#pragma unroll
        for (int t = 0; t < NTRI; t++) p[9 + t] = s2[t];
    }
    __syncthreads();

    for (int i = threadIdx.x; i < KK * MPK; i += 256) {
        float v = 0.0f;
#pragma unroll
        for (int w = 0; w < 8; w++) v += sacc[w][i];
        atomicAdd(&g_mom[i], (double)v);
    }

    // ---- last block runs stats inline (warp per component) ----
    __shared__ bool is_last;
    __threadfence();
    __syncthreads();
    if (threadIdx.x == 0) {
        unsigned prev = atomicAdd(&g_mctr, 1u);
        is_last = (prev == (unsigned)(gridDim.x - 1));
        if (is_last) g_mctr = 0u;      // reset for next replay
    }
    __syncthreads();
    if (!is_last) return;
    __threadfence();                    // acquire all g_mom writes

    {
        const int w = threadIdx.x >> 5;        // component k
        const int r = threadIdx.x & 31;        // lane; rows live in lanes 0..7
        __shared__ float s_cd[8];

        const double* mo = g_mom + w * MPK;
        const float gsf = (float)mo[0];
        const float rgs = 1.0f / gsf;

        float mu[8];
#pragma unroll
        for (int j = 0; j < 8; j++) mu[j] = (float)mo[1 + j] * rgs;

        float ar[8], ir[8];
        float cd = 0.0f;
        if (r < 8) {
#pragma unroll
            for (int j = 0; j < 8; j++) {
                int i0 = r < j ? r : j;
                int j0 = r < j ? j : r;
                int t = TRI_ROW[i0] + (j0 - i0);
                ar[j] = fmaf(-mu[r], mu[j], (float)mo[9 + t] * rgs);
                ir[j] = (r == j) ? 1.0f : 0.0f;
            }
            ar[r] += 1e-12f;                   // EPS*I, matches reference
            cd = 1.0f / ar[r];
        } else {
#pragma unroll
            for (int j = 0; j < 8; j++) { ar[j] = (r == j + 24) ? 1.0f : 0.0f; ir[j] = 0.0f; }
        }

        float det = 1.0f;
#pragma unroll
        for (int p = 0; p < 8; p++) {
            float piv = __shfl_sync(m, ar[p], p);
            det *= piv;
            float rc = 1.0f / piv;
            float par[8], pir[8];
#pragma unroll
            for (int j = 0; j < 8; j++) par[j] = __shfl_sync(m, ar[j], p) * rc;
#pragma unroll
            for (int j = 0; j < 8; j++) pir[j] = __shfl_sync(m, ir[j], p) * rc;
            float f = ar[p];
            if (r == p) {
#pragma unroll
                for (int j = 0; j < 8; j++) { ar[j] = par[j]; ir[j] = pir[j]; }
            } else {
#pragma unroll
                for (int j = 0; j < 8; j++) {
                    ar[j] = fmaf(-f, par[j], ar[j]);
                    ir[j] = fmaf(-f, pir[j], ir[j]);
                }
            }
        }

        float cstp = 0.0f;
        if (r < 8) {
#pragma unroll
            for (int j = 0; j < 8; j++) {
                if (j >= r) {
                    int t = TRI_ROW[r] + (j - r);
                    g_w2[w * NTRI + t] = (j == r) ? (-0.5f * ir[r]) : (-ir[j]);
                }
            }
            float b = 0.0f;
#pragma unroll
            for (int j = 0; j < 8; j++) b = fmaf(ir[j], mu[j], b);
            g_bv[w * DD + r] = b;
            cstp = b * mu[r];
        }
#pragma unroll
        for (int o = 4; o > 0; o >>= 1) {
            cstp += __shfl_xor_sync(m, cstp, o);
            cd   += __shfl_xor_sync(m, cd, o);
        }
        if (r == 0) {
            float phi = gsf * (1.0f / (float)NS);
            float ck = phi / (39.478417604357434f * sqrtf(sqrtf(det)));
            g_cst[w] = -0.5f * cstp + logf(ck);
            s_cd[w] = cd;
        }
        __syncthreads();
        if (threadIdx.x == 0) {
            float cdt = 0.0f;
#pragma unroll
            for (int i = 0; i < 8; i++) cdt += s_cd[i];
            g_base = LAMBDA_COV * (double)cdt;   // reconst term added at finalize
        }
        // implicit kernel-end memory flush orders these writes before the
        // energy kernel launch on the same stream
    }
}

// ---------------- side stream: energy (z L2-resident after moments) --------
__global__ void __launch_bounds__(256, 2) energy_kernel(const float* __restrict__ z,
                                                        float* __restrict__ out) {
    const int lane = threadIdx.x & 31;
    const int k = lane & 7;

    float w[NTRI], bv[DD], cst;
#pragma unroll
    for (int t = 0; t < NTRI; t++) w[t] = g_w2[k * NTRI + t];
#pragma unroll
    for (int i = 0; i < DD; i++) bv[i] = g_bv[k * DD + i];
    cst = g_cst[k];

    const int slot = (blockIdx.x * blockDim.x + threadIdx.x) >> 3;
    const int stride = (gridDim.x * blockDim.x) >> 3;
    const unsigned m = 0xFFFFFFFFu;

    float acc = 0.0f;
#pragma unroll 2
    for (int n = slot; n < NS; n += stride) {
        float4 z0 = *reinterpret_cast<const float4*>(z + (size_t)n * 8);
        float4 z1 = *reinterpret_cast<const float4*>(z + (size_t)n * 8 + 4);
        float zz[8] = {z0.x, z0.y, z0.z, z0.w, z1.x, z1.y, z1.z, z1.w};

        float q = cst;
        int t = 0;
#pragma unroll
        for (int i = 0; i < 8; i++) {
            float row = bv[i];
#pragma unroll
            for (int j = i; j < 8; j++) { row = fmaf(w[t], zz[j], row); t++; }
            q = fmaf(zz[i], row, q);
        }
        float e = __expf(q);
        e += __shfl_xor_sync(m, e, 1);
        e += __shfl_xor_sync(m, e, 2);
        e += __shfl_xor_sync(m, e, 4);
        if (k == 0) acc += -__logf(e + 1e-12f);
    }

    __shared__ float red[8];
    float v = warp_reduce(acc);
    int wid = threadIdx.x >> 5;
    if (lane == 0) red[wid] = v;
    __syncthreads();
    if (threadIdx.x == 0) {
        float s = 0.0f;
#pragma unroll
        for (int i = 0; i < 8; i++) s += red[i];
        atomicAdd(&g_energy, (double)s);
    }
    finish_and_maybe_finalize(out);
}

// ---------------- launch: fork stream overlap, finalize-in-last-block ------
static cudaStream_t s_side = nullptr;
static cudaEvent_t s_fork = nullptr, s_join = nullptr;

extern "C" void kernel_launch(void* const* d_in, const int* in_sizes, int n_in,
                              void* d_out, int out_size) {
    const float* x     = (const float*)d_in[0];
    const float* xh    = (const float*)d_in[1];
    const float* z     = (const float*)d_in[2];
    const float* gamma = (const float*)d_in[3];
    float* out = (float*)d_out;

    if (s_side == nullptr) {
        int lo, hi;
        cudaDeviceGetStreamPriorityRange(&lo, &hi);
        cudaStreamCreateWithPriority(&s_side, cudaStreamNonBlocking, hi);
        cudaEventCreateWithFlags(&s_fork, cudaEventDisableTiming);
        cudaEventCreateWithFlags(&s_join, cudaEventDisableTiming);
    }

    // fork: high-priority side stream runs moments -> energy while main
    // stream runs reconst. Grids sized so all three share the register file.
    cudaEventRecord(s_fork, 0);
    cudaStreamWaitEvent(s_side, s_fork, 0);
    moments_kernel<<<MOMENT_BLOCKS, 256, 0, s_side>>>(z, gamma);
    energy_kernel<<<ENERGY_BLOCKS, 256, 0, s_side>>>(z, out);
    reconst_kernel<<<RECONST_BLOCKS, 256>>>((const float4*)x, (const float4*)xh, out);
    // join so the harness's stream sees side-stream completion (d_out written
    // potentially by energy's last block)
    cudaEventRecord(s_join, s_side);
    cudaStreamWaitEvent(0, s_join, 0);
}

// round 11
// speedup vs baseline: 1.2043x; 1.2043x over previous
#include <cuda_runtime.h>

// Problem constants (fixed shapes from reference setup_inputs)
#define NS   262144      // B*T*C samples
#define NEL  16777216    // B*T*C*F elements for reconstruction loss
#define KK   8           // mixture components
#define DD   8           // latent dim
#define NTRI 36          // D*(D+1)/2 upper-triangular entries
#define MPK  45          // per-k moment slots: gsum(1) + sz(8) + s2(36)

#define LAMBDA_ENERGY 0.1
#define LAMBDA_COV    0.005

#define NB 296           // 2 blocks/SM x 148 SMs: ALL blocks co-resident
                         // (launch_bounds(512,2) -> <=64 regs, 12KB smem)

// named barriers: 1 = moments/energy half (warps 8-15), 2 = reconst half
#define BAR_M() asm volatile("bar.sync 1, 256;" ::: "memory")
#define BAR_R() asm volatile("bar.sync 2, 256;" ::: "memory")

// ---------------- device scratch (zero-initialized at module load; the
// final block re-zeroes everything dirtied, so each graph replay starts
// clean) ----------------
__device__ double g_mom[KK * MPK];   // [k][0]=gsum, [1..8]=sum(g*z), [9..44]=sum(g*zi*zj)
__device__ double g_reconst;         // sum of squared diffs
__device__ double g_energy;          // sum of per-sample energies
__device__ double g_base;            // lambda_cov*cov_diag (overwritten each run)
__device__ float  g_w2[KK * NTRI];   // quad coeffs (overwritten each run before read)
__device__ float  g_bv[KK * DD];     // C*mu (overwritten)
__device__ float  g_cst[KK];         // -0.5*mu^T C mu + log(c_k) (overwritten)
__device__ unsigned g_mctr;          // moments-half arrival counter
__device__ unsigned g_done;          // block completion counter
__device__ volatile unsigned g_sense; // stats-ready release flag

// upper-tri row starts for D=8: t(i,j) = TRI_ROW[i] + (j - i), j >= i
__device__ __constant__ int TRI_ROW[8] = {0, 8, 15, 21, 26, 30, 33, 35};

__device__ __forceinline__ float warp_reduce(float v) {
#pragma unroll
    for (int o = 16; o > 0; o >>= 1) v += __shfl_xor_sync(0xFFFFFFFFu, v, o);
    return v;
}

__global__ void __launch_bounds__(512, 2) dagmm_kernel(
    const float4* __restrict__ x, const float4* __restrict__ xh,
    const float* __restrict__ z, const float* __restrict__ gamma,
    float* __restrict__ out) {
    const int tid  = threadIdx.x;
    const int lane = tid & 31;
    const int warp = tid >> 5;           // 0..15
    const unsigned m = 0xFFFFFFFFu;

    __shared__ float sacc[8][KK * MPK];  // 11.5 KB (moments half only)
    __shared__ float red_r[8], red_e[8], s_cd[8];
    __shared__ unsigned s_last;

    if (warp < 8) {
        // ============ RECONST HALF: warps 0-7 stream 128 MB ============
        const int n4 = NEL / 4;
        float acc0 = 0.0f, acc1 = 0.0f, acc2 = 0.0f, acc3 = 0.0f;
        int i = blockIdx.x * 256 + tid;
        const int stride = NB * 256;
        for (; i + 3 * stride < n4; i += 4 * stride) {
            float4 a0 = x[i],              b0 = xh[i];
            float4 a1 = x[i + stride],     b1 = xh[i + stride];
            float4 a2 = x[i + 2 * stride], b2 = xh[i + 2 * stride];
            float4 a3 = x[i + 3 * stride], b3 = xh[i + 3 * stride];
            float d;
            d = b0.x - a0.x; acc0 = fmaf(d, d, acc0);
            d = b0.y - a0.y; acc0 = fmaf(d, d, acc0);
            d = b0.z - a0.z; acc0 = fmaf(d, d, acc0);
            d = b0.w - a0.w; acc0 = fmaf(d, d, acc0);
            d = b1.x - a1.x; acc1 = fmaf(d, d, acc1);
            d = b1.y - a1.y; acc1 = fmaf(d, d, acc1);
            d = b1.z - a1.z; acc1 = fmaf(d, d, acc1);
            d = b1.w - a1.w; acc1 = fmaf(d, d, acc1);
            d = b2.x - a2.x; acc2 = fmaf(d, d, acc2);
            d = b2.y - a2.y; acc2 = fmaf(d, d, acc2);
            d = b2.z - a2.z; acc2 = fmaf(d, d, acc2);
            d = b2.w - a2.w; acc2 = fmaf(d, d, acc2);
            d = b3.x - a3.x; acc3 = fmaf(d, d, acc3);
            d = b3.y - a3.y; acc3 = fmaf(d, d, acc3);
            d = b3.z - a3.z; acc3 = fmaf(d, d, acc3);
            d = b3.w - a3.w; acc3 = fmaf(d, d, acc3);
        }
        for (; i < n4; i += stride) {
            float4 a = x[i], b = xh[i];
            float d;
            d = b.x - a.x; acc0 = fmaf(d, d, acc0);
            d = b.y - a.y; acc0 = fmaf(d, d, acc0);
            d = b.z - a.z; acc0 = fmaf(d, d, acc0);
            d = b.w - a.w; acc0 = fmaf(d, d, acc0);
        }
        float v = warp_reduce((acc0 + acc1) + (acc2 + acc3));
        if (lane == 0) red_r[warp] = v;
        BAR_R();
        if (tid == 0) {
            float s = 0.0f;
#pragma unroll
            for (int w = 0; w < 8; w++) s += red_r[w];
            atomicAdd(&g_reconst, (double)s);
            __threadfence();
        }
    } else {
        // ============ MOMENTS -> STATS -> ENERGY HALF: warps 8-15 ============
        const int mtid = tid - 256;          // 0..255
        const int wm = warp - 8;             // 0..7
        const int k = lane & 7;

        // ---- phase A: moments ----
        {
            const int slot = blockIdx.x * 32 + (mtid >> 3);
            const int stride = NB * 32;

            float gs = 0.0f;
            float sz[DD];
            float s2[NTRI];
#pragma unroll
            for (int i = 0; i < DD; i++) sz[i] = 0.0f;
#pragma unroll
            for (int t = 0; t < NTRI; t++) s2[t] = 0.0f;

            for (int n = slot; n < NS; n += stride) {
                float4 z0 = *reinterpret_cast<const float4*>(z + (size_t)n * 8);
                float4 z1 = *reinterpret_cast<const float4*>(z + (size_t)n * 8 + 4);
                float zz[8] = {z0.x, z0.y, z0.z, z0.w, z1.x, z1.y, z1.z, z1.w};
                float g = __ldg(gamma + (size_t)n * 8 + k);
                gs += g;
                float gz[8];
#pragma unroll
                for (int i = 0; i < 8; i++) { gz[i] = g * zz[i]; sz[i] += gz[i]; }
                int t = 0;
#pragma unroll
                for (int i = 0; i < 8; i++)
#pragma unroll
                    for (int j = i; j < 8; j++) { s2[t] = fmaf(gz[i], zz[j], s2[t]); t++; }
            }

            gs += __shfl_xor_sync(m, gs, 8);  gs += __shfl_xor_sync(m, gs, 16);
#pragma unroll
            for (int i = 0; i < DD; i++) {
                sz[i] += __shfl_xor_sync(m, sz[i], 8);
                sz[i] += __shfl_xor_sync(m, sz[i], 16);
            }
#pragma unroll
            for (int t = 0; t < NTRI; t++) {
                s2[t] += __shfl_xor_sync(m, s2[t], 8);
                s2[t] += __shfl_xor_sync(m, s2[t], 16);
            }

            if (lane < 8) {
                float* p = &sacc[wm][k * MPK];
                p[0] = gs;
#pragma unroll
                for (int i = 0; i < DD; i++) p[1 + i] = sz[i];
#pragma unroll
                for (int t = 0; t < NTRI; t++) p[9 + t] = s2[t];
            }
            BAR_M();

            for (int i = mtid; i < KK * MPK; i += 256) {
                float v = 0.0f;
#pragma unroll
                for (int w = 0; w < 8; w++) v += sacc[w][i];
                atomicAdd(&g_mom[i], (double)v);
            }
            __threadfence();
            BAR_M();
        }

        // ---- arrival counter: straggler block's half runs stats ----
        __shared__ unsigned s_strag;
        if (mtid == 0) {
            unsigned prev = atomicAdd(&g_mctr, 1u);
            s_strag = (prev == (unsigned)(NB - 1)) ? 1u : 0u;
            if (s_strag) g_mctr = 0u;   // reset for next replay
        }
        BAR_M();

        if (s_strag) {
            // ---- stats: warp wm = component, lanes 0..7 = matrix rows ----
            const int w = wm;
            const int r = lane;
            __threadfence();             // acquire all g_mom writes

            const double* mo = g_mom + w * MPK;
            const float gsf = (float)mo[0];
            const float rgs = 1.0f / gsf;

            float mu[8];
#pragma unroll
            for (int j = 0; j < 8; j++) mu[j] = (float)mo[1 + j] * rgs;

            float ar[8], ir[8];
            float cd = 0.0f;
            if (r < 8) {
#pragma unroll
                for (int j = 0; j < 8; j++) {
                    int i0 = r < j ? r : j;
                    int j0 = r < j ? j : r;
                    int t = TRI_ROW[i0] + (j0 - i0);
                    ar[j] = fmaf(-mu[r], mu[j], (float)mo[9 + t] * rgs);
                    ir[j] = (r == j) ? 1.0f : 0.0f;
                }
                ar[r] += 1e-12f;         // EPS*I, matches reference
                cd = 1.0f / ar[r];
            } else {
#pragma unroll
                for (int j = 0; j < 8; j++) { ar[j] = (r == j + 24) ? 1.0f : 0.0f; ir[j] = 0.0f; }
            }

            float det = 1.0f;
#pragma unroll
            for (int p = 0; p < 8; p++) {
                float piv = __shfl_sync(m, ar[p], p);
                det *= piv;
                float rc = 1.0f / piv;
                float par[8], pir[8];
#pragma unroll
                for (int j = 0; j < 8; j++) par[j] = __shfl_sync(m, ar[j], p) * rc;
#pragma unroll
                for (int j = 0; j < 8; j++) pir[j] = __shfl_sync(m, ir[j], p) * rc;
                float f = ar[p];
                if (r == p) {
#pragma unroll
                    for (int j = 0; j < 8; j++) { ar[j] = par[j]; ir[j] = pir[j]; }
                } else {
#pragma unroll
                    for (int j = 0; j < 8; j++) {
                        ar[j] = fmaf(-f, par[j], ar[j]);
                        ir[j] = fmaf(-f, pir[j], ir[j]);
                    }
                }
            }

            float cstp = 0.0f;
            if (r < 8) {
#pragma unroll
                for (int j = 0; j < 8; j++) {
                    if (j >= r) {
                        int t = TRI_ROW[r] + (j - r);
                        g_w2[w * NTRI + t] = (j == r) ? (-0.5f * ir[r]) : (-ir[j]);
                    }
                }
                float b = 0.0f;
#pragma unroll
                for (int j = 0; j < 8; j++) b = fmaf(ir[j], mu[j], b);
                g_bv[w * DD + r] = b;
                cstp = b * mu[r];
            }
#pragma unroll
            for (int o = 4; o > 0; o >>= 1) {
                cstp += __shfl_xor_sync(m, cstp, o);
                cd   += __shfl_xor_sync(m, cd, o);
            }
            if (r == 0) {
                float phi = gsf * (1.0f / (float)NS);
                float ck = phi / (39.478417604357434f * sqrtf(sqrtf(det)));
                g_cst[w] = -0.5f * cstp + logf(ck);
                s_cd[w] = cd;
            }
            __threadfence();             // each writer flushes its stats writes
            BAR_M();
            if (mtid == 0) {
                float cdt = 0.0f;
#pragma unroll
                for (int i = 0; i < 8; i++) cdt += s_cd[i];
                g_base = LAMBDA_COV * (double)cdt;
                __threadfence();
                g_sense = 1u;            // release all blocks
            }
            BAR_M();
        } else {
            if (mtid == 0) {
                while (g_sense < 1u) __nanosleep(64);
                __threadfence();         // acquire stats writes
            }
            BAR_M();
        }

        // ---- phase B: energy (z is L2-resident from phase A) ----
        {
            float w[NTRI], bv[DD], cst;
#pragma unroll
            for (int t = 0; t < NTRI; t++) w[t] = g_w2[k * NTRI + t];
#pragma unroll
            for (int i = 0; i < DD; i++) bv[i] = g_bv[k * DD + i];
            cst = g_cst[k];

            const int slot = blockIdx.x * 32 + (mtid >> 3);
            const int stride = NB * 32;

            float acc = 0.0f;
            for (int n = slot; n < NS; n += stride) {
                float4 z0 = *reinterpret_cast<const float4*>(z + (size_t)n * 8);
                float4 z1 = *reinterpret_cast<const float4*>(z + (size_t)n * 8 + 4);
                float zz[8] = {z0.x, z0.y, z0.z, z0.w, z1.x, z1.y, z1.z, z1.w};

                float q = cst;
                int t = 0;
#pragma unroll
                for (int i = 0; i < 8; i++) {
                    float row = bv[i];
#pragma unroll
                    for (int j = i; j < 8; j++) { row = fmaf(w[t], zz[j], row); t++; }
                    q = fmaf(zz[i], row, q);
                }
                float e = __expf(q);
                e += __shfl_xor_sync(m, e, 1);
                e += __shfl_xor_sync(m, e, 2);
                e += __shfl_xor_sync(m, e, 4);
                if (k == 0) acc += -__logf(e + 1e-12f);
            }

            float v = warp_reduce(acc);
            if (lane == 0) red_e[wm] = v;
            BAR_M();
            if (mtid == 0) {
                float s = 0.0f;
#pragma unroll
                for (int i = 0; i < 8; i++) s += red_e[i];
                atomicAdd(&g_energy, (double)s);
                __threadfence();
            }
        }
    }

    // ============ full-block join + last-block finalize ============
    __syncthreads();
    if (tid == 0)
        s_last = (atomicAdd(&g_done, 1u) == (unsigned)(NB - 1)) ? 1u : 0u;
    __syncthreads();
    if (s_last) {
        if (tid == 0) {
            __threadfence();
            double rm = g_reconst / (double)NEL;
            double e  = *((volatile double*)&g_energy);
            out[0] = (float)(rm + g_base + LAMBDA_ENERGY * (e / (double)NS));
            g_reconst = 0.0;
            g_energy = 0.0;
            g_done = 0u;
            g_sense = 0u;
        }
        for (int i = tid; i < KK * MPK; i += 512) g_mom[i] = 0.0;
    }
}

// ---------------- launch: ONE kernel, warp-specialized overlap ----------------
extern "C" void kernel_launch(void* const* d_in, const int* in_sizes, int n_in,
                              void* d_out, int out_size) {
    const float* x     = (const float*)d_in[0];
    const float* xh    = (const float*)d_in[1];
    const float* z     = (const float*)d_in[2];
    const float* gamma = (const float*)d_in[3];
    float* out = (float*)d_out;

    dagmm_kernel<<<NB, 512>>>((const float4*)x, (const float4*)xh, z, gamma, out);
}

// round 12
// speedup vs baseline: 1.3287x; 1.1033x over previous
#include <cuda_runtime.h>

// Problem constants (fixed shapes from reference setup_inputs)
#define NS   262144      // B*T*C samples
#define NEL  16777216    // B*T*C*F elements for reconstruction loss
#define KK   8           // mixture components
#define DD   8           // latent dim
#define NTRI 36          // D*(D+1)/2 upper-triangular entries
#define MPK  45          // per-k moment slots: gsum(1) + sz(8) + s2(36)

#define LAMBDA_ENERGY 0.1
#define LAMBDA_COV    0.005

#define RECONST_BLOCKS 888    // 6 blocks/SM @32regs
#define MOMENT_BLOCKS  444    // 3 blocks/SM @~85regs (unrolled for MLP)
#define ENERGY_BLOCKS  444
#define DONE_TARGET    (RECONST_BLOCKS + ENERGY_BLOCKS)

// ---------------- device scratch (zero-initialized at module load; the
// finalizing block re-zeroes everything dirtied, so each graph replay starts
// clean without a zeroing launch) ----------------
__device__ double g_mom[KK * MPK];   // [k][0]=gsum, [1..8]=sum(g*z), [9..44]=sum(g*zi*zj)
__device__ double g_reconst;         // sum of squared diffs
__device__ double g_energy;          // sum of per-sample energies
__device__ double g_base;            // lambda_cov*cov_diag (overwritten each run)
__device__ float  g_w2[KK * NTRI];   // quad coeffs (overwritten each run)
__device__ float  g_bv[KK * DD];     // C*mu (overwritten)
__device__ float  g_cst[KK];         // -0.5*mu^T C mu + log(c_k) (overwritten)
__device__ unsigned g_mctr;          // moments last-block counter
__device__ unsigned g_done;          // completion counter (reconst + energy blocks)

// upper-tri row starts for D=8: t(i,j) = TRI_ROW[i] + (j - i), j >= i
__device__ __constant__ int TRI_ROW[8] = {0, 8, 15, 21, 26, 30, 33, 35};

__device__ __forceinline__ float warp_reduce(float v) {
#pragma unroll
    for (int o = 16; o > 0; o >>= 1) v += __shfl_xor_sync(0xFFFFFFFFu, v, o);
    return v;
}

// finalize-if-last: the globally LAST terminal block (reconst or energy)
// writes the scalar and resets all replay state. g_base is valid because
// stats ran (in moments' last block) before any energy block could finish.
__device__ __forceinline__ void finish_and_maybe_finalize(float* out) {
    __shared__ unsigned s_last;
    if (threadIdx.x == 0) {
        __threadfence();
        unsigned prev = atomicAdd(&g_done, 1u);
        s_last = (prev == (unsigned)(DONE_TARGET - 1)) ? 1u : 0u;
    }
    __syncthreads();
    if (s_last) {
        if (threadIdx.x == 0) {
            __threadfence();
            double rm = g_reconst / (double)NEL;
            double e  = *((volatile double*)&g_energy);
            out[0] = (float)(rm + g_base + LAMBDA_ENERGY * (e / (double)NS));
            g_reconst = 0.0;
            g_energy = 0.0;
            g_done = 0u;
        }
        for (int i = threadIdx.x; i < KK * MPK; i += blockDim.x) g_mom[i] = 0.0;
    }
}

// ---------------- main stream: reconstruction sum (pure HBM stream) --------
__global__ void __launch_bounds__(256, 6) reconst_kernel(
    const float4* __restrict__ x, const float4* __restrict__ xh,
    float* __restrict__ out) {
    const int n4 = NEL / 4;
    float acc0 = 0.0f, acc1 = 0.0f;
    int i = blockIdx.x * 256 + threadIdx.x;
    const int stride = RECONST_BLOCKS * 256;
    for (; i + stride < n4; i += 2 * stride) {
        float4 a0 = x[i], b0 = xh[i];
        float4 a1 = x[i + stride], b1 = xh[i + stride];
        float d;
        d = b0.x - a0.x; acc0 = fmaf(d, d, acc0);
        d = b0.y - a0.y; acc0 = fmaf(d, d, acc0);
        d = b0.z - a0.z; acc0 = fmaf(d, d, acc0);
        d = b0.w - a0.w; acc0 = fmaf(d, d, acc0);
        d = b1.x - a1.x; acc1 = fmaf(d, d, acc1);
        d = b1.y - a1.y; acc1 = fmaf(d, d, acc1);
        d = b1.z - a1.z; acc1 = fmaf(d, d, acc1);
        d = b1.w - a1.w; acc1 = fmaf(d, d, acc1);
    }
    for (; i < n4; i += stride) {
        float4 a = x[i], b = xh[i];
        float d;
        d = b.x - a.x; acc0 = fmaf(d, d, acc0);
        d = b.y - a.y; acc0 = fmaf(d, d, acc0);
        d = b.z - a.z; acc0 = fmaf(d, d, acc0);
        d = b.w - a.w; acc0 = fmaf(d, d, acc0);
    }
    __shared__ float red[8];
    float v = warp_reduce(acc0 + acc1);
    int lane = threadIdx.x & 31, wid = threadIdx.x >> 5;
    if (lane == 0) red[wid] = v;
    __syncthreads();
    if (threadIdx.x == 0) {
        float s = 0.0f;
#pragma unroll
        for (int w = 0; w < 8; w++) s += red[w];
        atomicAdd(&g_reconst, (double)s);
    }
    finish_and_maybe_finalize(out);
}

// ---------------- side stream: GMM moments (2x unrolled for MLP) -----------
// 8 lanes per sample-slot (one per k); two samples' loads front-batched per
// iteration so each thread keeps ~72B of DRAM traffic in flight.
__global__ void __launch_bounds__(256, 3) moments_kernel(
    const float* __restrict__ z, const float* __restrict__ gamma) {
    const int lane = threadIdx.x & 31;
    const int k = lane & 7;
    const int warp = threadIdx.x >> 5;                 // 0..7
    const int slot = (blockIdx.x * 256 + threadIdx.x) >> 3;
    const int stride = (MOMENT_BLOCKS * 256) >> 3;

    float gs = 0.0f;
    float sz[DD];
    float s2[NTRI];
#pragma unroll
    for (int i = 0; i < DD; i++) sz[i] = 0.0f;
#pragma unroll
    for (int t = 0; t < NTRI; t++) s2[t] = 0.0f;

    int n = slot;
    for (; n + stride < NS; n += 2 * stride) {
        // front-batched loads: 4x LDG.128 + 2x LDG.32 in flight
        float4 a0 = *reinterpret_cast<const float4*>(z + (size_t)n * 8);
        float4 a1 = *reinterpret_cast<const float4*>(z + (size_t)n * 8 + 4);
        float4 b0 = *reinterpret_cast<const float4*>(z + (size_t)(n + stride) * 8);
        float4 b1 = *reinterpret_cast<const float4*>(z + (size_t)(n + stride) * 8 + 4);
        float ga = __ldg(gamma + (size_t)n * 8 + k);
        float gb = __ldg(gamma + (size_t)(n + stride) * 8 + k);

        {
            float zz[8] = {a0.x, a0.y, a0.z, a0.w, a1.x, a1.y, a1.z, a1.w};
            gs += ga;
            float gz[8];
#pragma unroll
            for (int i = 0; i < 8; i++) { gz[i] = ga * zz[i]; sz[i] += gz[i]; }
            int t = 0;
#pragma unroll
            for (int i = 0; i < 8; i++)
#pragma unroll
                for (int j = i; j < 8; j++) { s2[t] = fmaf(gz[i], zz[j], s2[t]); t++; }
        }
        {
            float zz[8] = {b0.x, b0.y, b0.z, b0.w, b1.x, b1.y, b1.z, b1.w};
            gs += gb;
            float gz[8];
#pragma unroll
            for (int i = 0; i < 8; i++) { gz[i] = gb * zz[i]; sz[i] += gz[i]; }
            int t = 0;
#pragma unroll
            for (int i = 0; i < 8; i++)
#pragma unroll
                for (int j = i; j < 8; j++) { s2[t] = fmaf(gz[i], zz[j], s2[t]); t++; }
        }
    }
    for (; n < NS; n += stride) {
        float4 a0 = *reinterpret_cast<const float4*>(z + (size_t)n * 8);
        float4 a1 = *reinterpret_cast<const float4*>(z + (size_t)n * 8 + 4);
        float g = __ldg(gamma + (size_t)n * 8 + k);
        float zz[8] = {a0.x, a0.y, a0.z, a0.w, a1.x, a1.y, a1.z, a1.w};
        gs += g;
        float gz[8];
#pragma unroll
        for (int i = 0; i < 8; i++) { gz[i] = g * zz[i]; sz[i] += gz[i]; }
        int t = 0;
#pragma unroll
        for (int i = 0; i < 8; i++)
#pragma unroll
            for (int j = i; j < 8; j++) { s2[t] = fmaf(gz[i], zz[j], s2[t]); t++; }
    }

    const unsigned m = 0xFFFFFFFFu;
    gs += __shfl_xor_sync(m, gs, 8);  gs += __shfl_xor_sync(m, gs, 16);
#pragma unroll
    for (int i = 0; i < DD; i++) {
        sz[i] += __shfl_xor_sync(m, sz[i], 8);
        sz[i] += __shfl_xor_sync(m, sz[i], 16);
    }
#pragma unroll
    for (int t = 0; t < NTRI; t++) {
        s2[t] += __shfl_xor_sync(m, s2[t], 8);
        s2[t] += __shfl_xor_sync(m, s2[t], 16);
    }

    __shared__ float sacc[8][KK * MPK];   // 11.5 KB
    if (lane < 8) {
        float* p = &sacc[warp][k * MPK];
        p[0] = gs;
#pragma unroll
        for (int i = 0; i < DD; i++) p[1 + i] = sz[i];
#pragma unroll
        for (int t = 0; t < NTRI; t++) p[9 + t] = s2[t];
    }
    __syncthreads();

    for (int i = threadIdx.x; i < KK * MPK; i += 256) {
        float v = 0.0f;
#pragma unroll
        for (int w = 0; w < 8; w++) v += sacc[w][i];
        atomicAdd(&g_mom[i], (double)v);
    }

    // ---- last block runs stats inline (warp per component) ----
    __shared__ bool is_last;
    __threadfence();
    __syncthreads();
    if (threadIdx.x == 0) {
        unsigned prev = atomicAdd(&g_mctr, 1u);
        is_last = (prev == (unsigned)(gridDim.x - 1));
        if (is_last) g_mctr = 0u;      // reset for next replay
    }
    __syncthreads();
    if (!is_last) return;
    __threadfence();                    // acquire all g_mom writes

    {
        const int w = threadIdx.x >> 5;        // component k
        const int r = threadIdx.x & 31;        // lane; rows live in lanes 0..7
        __shared__ float s_cd[8];

        const double* mo = g_mom + w * MPK;
        const float gsf = (float)mo[0];
        const float rgs = 1.0f / gsf;

        float mu[8];
#pragma unroll
        for (int j = 0; j < 8; j++) mu[j] = (float)mo[1 + j] * rgs;

        float ar[8], ir[8];
        float cd = 0.0f;
        if (r < 8) {
#pragma unroll
            for (int j = 0; j < 8; j++) {
                int i0 = r < j ? r : j;
                int j0 = r < j ? j : r;
                int t = TRI_ROW[i0] + (j0 - i0);
                ar[j] = fmaf(-mu[r], mu[j], (float)mo[9 + t] * rgs);
                ir[j] = (r == j) ? 1.0f : 0.0f;
            }
            ar[r] += 1e-12f;                   // EPS*I, matches reference
            cd = 1.0f / ar[r];
        } else {
#pragma unroll
            for (int j = 0; j < 8; j++) { ar[j] = (r == j + 24) ? 1.0f : 0.0f; ir[j] = 0.0f; }
        }

        float det = 1.0f;
#pragma unroll
        for (int p = 0; p < 8; p++) {
            float piv = __shfl_sync(m, ar[p], p);
            det *= piv;
            float rc = 1.0f / piv;
            float par[8], pir[8];
#pragma unroll
            for (int j = 0; j < 8; j++) par[j] = __shfl_sync(m, ar[j], p) * rc;
#pragma unroll
            for (int j = 0; j < 8; j++) pir[j] = __shfl_sync(m, ir[j], p) * rc;
            float f = ar[p];
            if (r == p) {
#pragma unroll
                for (int j = 0; j < 8; j++) { ar[j] = par[j]; ir[j] = pir[j]; }
            } else {
#pragma unroll
                for (int j = 0; j < 8; j++) {
                    ar[j] = fmaf(-f, par[j], ar[j]);
                    ir[j] = fmaf(-f, pir[j], ir[j]);
                }
            }
        }

        float cstp = 0.0f;
        if (r < 8) {
#pragma unroll
            for (int j = 0; j < 8; j++) {
                if (j >= r) {
                    int t = TRI_ROW[r] + (j - r);
                    g_w2[w * NTRI + t] = (j == r) ? (-0.5f * ir[r]) : (-ir[j]);
                }
            }
            float b = 0.0f;
#pragma unroll
            for (int j = 0; j < 8; j++) b = fmaf(ir[j], mu[j], b);
            g_bv[w * DD + r] = b;
            cstp = b * mu[r];
        }
#pragma unroll
        for (int o = 4; o > 0; o >>= 1) {
            cstp += __shfl_xor_sync(m, cstp, o);
            cd   += __shfl_xor_sync(m, cd, o);
        }
        if (r == 0) {
            float phi = gsf * (1.0f / (float)NS);
            float ck = phi / (39.478417604357434f * sqrtf(sqrtf(det)));
            g_cst[w] = -0.5f * cstp + logf(ck);
            s_cd[w] = cd;
        }
        __syncthreads();
        if (threadIdx.x == 0) {
            float cdt = 0.0f;
#pragma unroll
            for (int i = 0; i < 8; i++) cdt += s_cd[i];
            g_base = LAMBDA_COV * (double)cdt;   // reconst term added at finalize
        }
    }
}

// ---------------- side stream: energy (2x unrolled; z L2-resident) ---------
__global__ void __launch_bounds__(256, 3) energy_kernel(const float* __restrict__ z,
                                                        float* __restrict__ out) {
    const int lane = threadIdx.x & 31;
    const int k = lane & 7;

    float w[NTRI], bv[DD], cst;
#pragma unroll
    for (int t = 0; t < NTRI; t++) w[t] = g_w2[k * NTRI + t];
#pragma unroll
    for (int i = 0; i < DD; i++) bv[i] = g_bv[k * DD + i];
    cst = g_cst[k];

    const int slot = (blockIdx.x * blockDim.x + threadIdx.x) >> 3;
    const int stride = (gridDim.x * blockDim.x) >> 3;
    const unsigned m = 0xFFFFFFFFu;

    float acc = 0.0f;
    int n = slot;
    for (; n + stride < NS; n += 2 * stride) {
        float4 a0 = *reinterpret_cast<const float4*>(z + (size_t)n * 8);
        float4 a1 = *reinterpret_cast<const float4*>(z + (size_t)n * 8 + 4);
        float4 b0 = *reinterpret_cast<const float4*>(z + (size_t)(n + stride) * 8);
        float4 b1 = *reinterpret_cast<const float4*>(z + (size_t)(n + stride) * 8 + 4);

        {
            float zz[8] = {a0.x, a0.y, a0.z, a0.w, a1.x, a1.y, a1.z, a1.w};
            float q = cst;
            int t = 0;
#pragma unroll
            for (int i = 0; i < 8; i++) {
                float row = bv[i];
#pragma unroll
                for (int j = i; j < 8; j++) { row = fmaf(w[t], zz[j], row); t++; }
                q = fmaf(zz[i], row, q);
            }
            float e = __expf(q);
            e += __shfl_xor_sync(m, e, 1);
            e += __shfl_xor_sync(m, e, 2);
            e += __shfl_xor_sync(m, e, 4);
            if (k == 0) acc += -__logf(e + 1e-12f);
        }
        {
            float zz[8] = {b0.x, b0.y, b0.z, b0.w, b1.x, b1.y, b1.z, b1.w};
            float q = cst;
            int t = 0;
#pragma unroll
            for (int i = 0; i < 8; i++) {
                float row = bv[i];
#pragma unroll
                for (int j = i; j < 8; j++) { row = fmaf(w[t], zz[j], row); t++; }
                q = fmaf(zz[i], row, q);
            }
            float e = __expf(q);
            e += __shfl_xor_sync(m, e, 1);
            e += __shfl_xor_sync(m, e, 2);
            e += __shfl_xor_sync(m, e, 4);
            if (k == 0) acc += -__logf(e + 1e-12f);
        }
    }
    for (; n < NS; n += stride) {
        float4 a0 = *reinterpret_cast<const float4*>(z + (size_t)n * 8);
        float4 a1 = *reinterpret_cast<const float4*>(z + (size_t)n * 8 + 4);
        float zz[8] = {a0.x, a0.y, a0.z, a0.w, a1.x, a1.y, a1.z, a1.w};
        float q = cst;
        int t = 0;
#pragma unroll
        for (int i = 0; i < 8; i++) {
            float row = bv[i];
#pragma unroll
            for (int j = i; j < 8; j++) { row = fmaf(w[t], zz[j], row); t++; }
            q = fmaf(zz[i], row, q);
        }
        float e = __expf(q);
        e += __shfl_xor_sync(m, e, 1);
        e += __shfl_xor_sync(m, e, 2);
        e += __shfl_xor_sync(m, e, 4);
        if (k == 0) acc += -__logf(e + 1e-12f);
    }

    __shared__ float red[8];
    float v = warp_reduce(acc);
    int wid = threadIdx.x >> 5;
    if (lane == 0) red[wid] = v;
    __syncthreads();
    if (threadIdx.x == 0) {
        float s = 0.0f;
#pragma unroll
        for (int i = 0; i < 8; i++) s += red[i];
        atomicAdd(&g_energy, (double)s);
    }
    finish_and_maybe_finalize(out);
}

// ---------------- launch: fork stream overlap, finalize-in-last-block ------
static cudaStream_t s_side = nullptr;
static cudaEvent_t s_fork = nullptr, s_join = nullptr;

extern "C" void kernel_launch(void* const* d_in, const int* in_sizes, int n_in,
                              void* d_out, int out_size) {
    const float* x     = (const float*)d_in[0];
    const float* xh    = (const float*)d_in[1];
    const float* z     = (const float*)d_in[2];
    const float* gamma = (const float*)d_in[3];
    float* out = (float*)d_out;

    if (s_side == nullptr) {
        int lo, hi;
        cudaDeviceGetStreamPriorityRange(&lo, &hi);
        cudaStreamCreateWithPriority(&s_side, cudaStreamNonBlocking, hi);
        cudaEventCreateWithFlags(&s_fork, cudaEventDisableTiming);
        cudaEventCreateWithFlags(&s_join, cudaEventDisableTiming);
    }

    // fork: side stream runs moments -> energy while main stream runs reconst.
    cudaEventRecord(s_fork, 0);
    cudaStreamWaitEvent(s_side, s_fork, 0);
    moments_kernel<<<MOMENT_BLOCKS, 256, 0, s_side>>>(z, gamma);
    energy_kernel<<<ENERGY_BLOCKS, 256, 0, s_side>>>(z, out);
    reconst_kernel<<<RECONST_BLOCKS, 256>>>((const float4*)x, (const float4*)xh, out);
    // join so the harness's stream sees side-stream completion
    cudaEventRecord(s_join, s_side);
    cudaStreamWaitEvent(0, s_join, 0);
}